// round 3
// baseline (speedup 1.0000x reference)
#include <cuda_runtime.h>
#include <cstdint>

#define ENTITYN 50000
#define EMBD    256
#define HIDD    256
#define BATCHN  64
#define LSEQ    256
#define NEDGE   800000

// ---------------- scratch (device globals: no allocation allowed) ----------------
__device__ float g_bufA[BATCHN * LSEQ * HIDD];        // 16.8 MB
__device__ float g_bufB[BATCHN * LSEQ * HIDD];        // 16.8 MB
__device__ float g_xi[BATCHN * LSEQ * 3 * HIDD];      // 50 MB
__device__ float g_WihT[HIDD * 3 * HIDD];             // [k][n] = Wih[n][k]
__device__ float g_WhhP[HIDD * 3 * HIDD];             // packed [k][j], row j contiguous
__device__ float g_fc1WT[HIDD * HIDD];                // [k][j] = fc1W[j][k]
__device__ float g_support[ENTITYN * HIDD];           // 51.2 MB (gated path)
__device__ float g_agg[ENTITYN * HIDD];               // 51.2 MB (gated path)
__device__ float g_hT[BATCHN * HIDD];

// Device-side buffer selector: keeps kernel_launch free of cudaGetSymbolAddress.
#define SEL_EXT     0
#define SEL_BUFA    1
#define SEL_BUFB    2
#define SEL_XI      3
#define SEL_WIHT    4
#define SEL_SUPPORT 5

__device__ __forceinline__ float* selptr(int s, const void* ext) {
    switch (s) {
        case SEL_BUFA:    return g_bufA;
        case SEL_BUFB:    return g_bufB;
        case SEL_XI:      return g_xi;
        case SEL_WIHT:    return g_WihT;
        case SEL_SUPPORT: return g_support;
        default:          return (float*)ext;
    }
}

// ---------------- weight prep: transposes + packing ----------------
__global__ void prep_kernel(const float* __restrict__ Wih,
                            const float* __restrict__ Whh,
                            const float* __restrict__ fc1W) {
    int stride = gridDim.x * blockDim.x;
    int t0 = blockIdx.x * blockDim.x + threadIdx.x;
    for (int i = t0; i < 256 * 768; i += stride) {
        int k = i / 768, n = i % 768;
        g_WihT[i] = Wih[n * 256 + k];
    }
    for (int i = t0; i < 256 * 768; i += stride) {
        int k = i / 768, r = i % 768;   // r = output row j
        g_WhhP[i] = Whh[r * 256 + k];
    }
    for (int i = t0; i < 256 * 256; i += stride) {
        int k = i / 256, j = i % 256;
        g_fc1WT[i] = fc1W[j * 256 + k];
    }
}

// ---------------- gated GNN path (only runs when eps != 0) ----------------
__global__ void zero_agg_kernel(const float* __restrict__ eps) {
    if (eps[0] == 0.0f) return;
    int stride = gridDim.x * blockDim.x;
    for (int i = blockIdx.x * blockDim.x + threadIdx.x; i < ENTITYN * HIDD; i += stride)
        g_agg[i] = 0.0f;
}

__global__ void scatter_kernel(const int* __restrict__ esrc,
                               const int* __restrict__ edst,
                               const float* __restrict__ ew,
                               const float* __restrict__ eps) {
    if (eps[0] == 0.0f) return;
    long stride = (long)gridDim.x * blockDim.x;
    long total = (long)NEDGE * 64;   // 64 float4 chunks per edge
    for (long i = (long)blockIdx.x * blockDim.x + threadIdx.x; i < total; i += stride) {
        int e = (int)(i >> 6);
        int c = ((int)i & 63) * 4;
        int s = esrc[e], d = edst[e];
        float w = ew[e];
        const float4 v = *(const float4*)&g_support[(long)s * 256 + c];
        float* dst = &g_agg[(long)d * 256 + c];
        atomicAdd(dst + 0, v.x * w);
        atomicAdd(dst + 1, v.y * w);
        atomicAdd(dst + 2, v.z * w);
        atomicAdd(dst + 3, v.w * w);
    }
}

// ---------------- generic tiled fp32 GEMM: C = A@B (+bias), optional row gather,
// optional batching (strides x blockIdx.z), optional eps gate
__global__ void __launch_bounds__(256) gemm64_kernel(
    int selA, const void* Aext, long strideA,
    int selB, const void* Bext, long strideB,
    int selC, void* Cext, long strideC,
    const float* __restrict__ bias,
    const int* __restrict__ gidx,
    const float* __restrict__ gate,
    int M, int N, int K)
{
    if (gate != nullptr && gate[0] == 0.0f) return;
    const float* A = selptr(selA, Aext) + (long)blockIdx.z * strideA;
    const float* B = selptr(selB, Bext) + (long)blockIdx.z * strideB;
    float*       C = selptr(selC, Cext) + (long)blockIdx.z * strideC;

    __shared__ float As[16][68];
    __shared__ float Bs[16][64];

    const int tid = threadIdx.x;
    const int m0 = blockIdx.y * 64, n0 = blockIdx.x * 64;
    const int tx = tid & 15, ty = tid >> 4;

    const int arow = tid >> 2;          // 0..63
    const int acol = (tid & 3) * 4;     // 0,4,8,12
    const int brow = tid >> 4;          // 0..15
    const int bcol = (tid & 15) * 4;    // 0..60

    const int am = m0 + arow;
    const bool avalid = (am < M);
    long arow_g = 0;
    if (avalid) arow_g = gidx ? (long)gidx[am] : (long)am;
    const float* Arow = A + arow_g * K + acol;

    float acc[4][4];
#pragma unroll
    for (int i = 0; i < 4; i++)
#pragma unroll
        for (int j = 0; j < 4; j++) acc[i][j] = 0.0f;

    for (int k0 = 0; k0 < K; k0 += 16) {
        float4 av = avalid ? *(const float4*)(Arow + k0)
                           : make_float4(0.f, 0.f, 0.f, 0.f);
        As[acol + 0][arow] = av.x;
        As[acol + 1][arow] = av.y;
        As[acol + 2][arow] = av.z;
        As[acol + 3][arow] = av.w;
        float4 bv = *(const float4*)(B + (long)(k0 + brow) * N + n0 + bcol);
        *(float4*)&Bs[brow][bcol] = bv;
        __syncthreads();
#pragma unroll
        for (int kk = 0; kk < 16; kk++) {
            float a0 = As[kk][ty * 4 + 0];
            float a1 = As[kk][ty * 4 + 1];
            float a2 = As[kk][ty * 4 + 2];
            float a3 = As[kk][ty * 4 + 3];
            float4 b = *(const float4*)&Bs[kk][tx * 4];
            acc[0][0] += a0 * b.x; acc[0][1] += a0 * b.y; acc[0][2] += a0 * b.z; acc[0][3] += a0 * b.w;
            acc[1][0] += a1 * b.x; acc[1][1] += a1 * b.y; acc[1][2] += a1 * b.z; acc[1][3] += a1 * b.w;
            acc[2][0] += a2 * b.x; acc[2][1] += a2 * b.y; acc[2][2] += a2 * b.z; acc[2][3] += a2 * b.w;
            acc[3][0] += a3 * b.x; acc[3][1] += a3 * b.y; acc[3][2] += a3 * b.z; acc[3][3] += a3 * b.w;
        }
        __syncthreads();
    }

    float4 bb = make_float4(0.f, 0.f, 0.f, 0.f);
    if (bias) bb = *(const float4*)(bias + n0 + tx * 4);
#pragma unroll
    for (int i = 0; i < 4; i++) {
        int m = m0 + ty * 4 + i;
        if (m < M) {
            float4 r = make_float4(acc[i][0] + bb.x, acc[i][1] + bb.y,
                                   acc[i][2] + bb.z, acc[i][3] + bb.w);
            *(float4*)(C + (long)m * N + n0 + tx * 4) = r;
        }
    }
}

// ---------------- eps mix: bufA = (1-eps)*bufB + eps*leaky(agg[cur]+bg) ----------------
__global__ void mix_kernel(const int* __restrict__ cur,
                           const float* __restrict__ bg,
                           const float* __restrict__ eps) {
    float e = eps[0];
    int stride = gridDim.x * blockDim.x;
    for (int i = blockIdx.x * blockDim.x + threadIdx.x; i < BATCHN * LSEQ * HIDD; i += stride) {
        float v = g_bufB[i];
        if (e != 0.0f) {
            int row = i >> 8, col = i & 255;
            int cn = cur[row];
            float a = g_agg[(long)cn * 256 + col] + bg[col];
            a = a > 0.0f ? a : 0.2f * a;
            v = (1.0f - e) * v + e * a;
        }
        g_bufA[i] = v;
    }
}

// ---------------- GRU: 32 blocks, 2 batch elements per block ----------------
__global__ void __launch_bounds__(256, 1) gru_kernel(const float* __restrict__ bhh) {
    __shared__ float h0[256], h1[256];
    __shared__ float gh0[768], gh1[768];
    __shared__ float sb[768];

    const int tid = threadIdx.x;
    const int b0 = blockIdx.x * 2, b1 = b0 + 1;

    h0[tid] = 0.0f;
    h1[tid] = 0.0f;
    for (int j = tid; j < 768; j += 256) sb[j] = bhh[j];
    __syncthreads();

    const float4* Wp = (const float4*)g_WhhP;   // [k][192] float4

    for (int t = 0; t < 256; t++) {
        if (tid < 192) {
            float a00 = 0.f, a01 = 0.f, a02 = 0.f, a03 = 0.f;
            float a10 = 0.f, a11 = 0.f, a12 = 0.f, a13 = 0.f;
            const float4* wp = Wp + tid;
#pragma unroll 16
            for (int k = 0; k < 256; k++) {
                float4 w = wp[k * 192];
                float x0 = h0[k], x1 = h1[k];
                a00 += w.x * x0; a01 += w.y * x0; a02 += w.z * x0; a03 += w.w * x0;
                a10 += w.x * x1; a11 += w.y * x1; a12 += w.z * x1; a13 += w.w * x1;
            }
            ((float4*)gh0)[tid] = make_float4(a00, a01, a02, a03);
            ((float4*)gh1)[tid] = make_float4(a10, a11, a12, a13);
        }
        __syncthreads();
        {
            const int j = tid;
            const float* xb0 = g_xi + ((long)b0 * 256 + t) * 768;
            const float* xb1 = g_xi + ((long)b1 * 256 + t) * 768;

            float ir = xb0[j], iz = xb0[256 + j], in0 = xb0[512 + j];
            float hr = gh0[j] + sb[j];
            float hz = gh0[256 + j] + sb[256 + j];
            float hn = gh0[512 + j] + sb[512 + j];
            float r = 1.0f / (1.0f + __expf(-(ir + hr)));
            float z = 1.0f / (1.0f + __expf(-(iz + hz)));
            float n = tanhf(in0 + r * hn);
            float hnew0 = (1.0f - z) * n + z * h0[j];

            ir = xb1[j]; iz = xb1[256 + j]; in0 = xb1[512 + j];
            hr = gh1[j] + sb[j];
            hz = gh1[256 + j] + sb[256 + j];
            hn = gh1[512 + j] + sb[512 + j];
            r = 1.0f / (1.0f + __expf(-(ir + hr)));
            z = 1.0f / (1.0f + __expf(-(iz + hz)));
            n = tanhf(in0 + r * hn);
            float hnew1 = (1.0f - z) * n + z * h1[j];

            h0[j] = hnew0;   // safe: only this thread touches h[j] in epilogue
            h1[j] = hnew1;
        }
        __syncthreads();
    }
    g_hT[(long)b0 * 256 + tid] = h0[tid];
    g_hT[(long)b1 * 256 + tid] = h1[tid];
}

// ---------------- final fc1 + relu ----------------
__global__ void fc_kernel(const float* __restrict__ fc1b, float* __restrict__ out) {
    __shared__ float hs[HIDD];
    const int b = blockIdx.x, j = threadIdx.x;
    hs[j] = g_hT[b * HIDD + j];
    __syncthreads();
    float acc = 0.0f;
#pragma unroll 8
    for (int k = 0; k < HIDD; k++) acc += hs[k] * g_fc1WT[k * HIDD + j];
    acc += fc1b[j];
    out[b * HIDD + j] = acc > 0.0f ? acc : 0.0f;
}

// ---------------- launcher: kernel launches ONLY, no other CUDA API ----------------
extern "C" void kernel_launch(void* const* d_in, const int* in_sizes, int n_in,
                              void* d_out, int out_size) {
    const int*   neighbors = (const int*)  d_in[0];
    const float* adj       = (const float*)d_in[1];
    const int*   cur_node  = (const int*)  d_in[2];
    const int*   edge_src  = (const int*)  d_in[3];
    const int*   edge_dst  = (const int*)  d_in[4];
    const float* edge_w    = (const float*)d_in[5];
    const float* emb       = (const float*)d_in[6];
    const float* Wg        = (const float*)d_in[7];
    const float* bg        = (const float*)d_in[8];
    const float* W1        = (const float*)d_in[9];
    const float* b1        = (const float*)d_in[10];
    const float* W2        = (const float*)d_in[11];
    const float* b2        = (const float*)d_in[12];
    const float* eps       = (const float*)d_in[13];
    const float* Wih       = (const float*)d_in[14];
    const float* Whh       = (const float*)d_in[15];
    const float* bih       = (const float*)d_in[16];
    const float* bhh       = (const float*)d_in[17];
    const float* fc1W      = (const float*)d_in[18];
    const float* fc1b      = (const float*)d_in[19];
    float* out = (float*)d_out;

    const int  MBL  = BATCHN * LSEQ;        // 16384
    const long SADJ = (long)LSEQ * LSEQ;    // 65536
    const long SX   = (long)LSEQ * HIDD;    // 65536

    // weight prep
    prep_kernel<<<256, 256>>>(Wih, Whh, fc1W);

    // gated global-GNN path (no-op when eps == 0)
    zero_agg_kernel<<<2048, 256>>>(eps);
    gemm64_kernel<<<dim3(4, (ENTITYN + 63) / 64, 1), 256>>>(
        SEL_EXT, emb, 0, SEL_EXT, Wg, 0, SEL_SUPPORT, nullptr, 0,
        nullptr, nullptr, eps, ENTITYN, 256, 256);
    scatter_kernel<<<4096, 256>>>(edge_src, edge_dst, edge_w, eps);

    // bufA = emb[neighbors] @ W1
    gemm64_kernel<<<dim3(4, MBL / 64, 1), 256>>>(
        SEL_EXT, emb, 0, SEL_EXT, W1, 0, SEL_BUFA, nullptr, 0,
        nullptr, neighbors, nullptr, MBL, 256, 256);
    // bufB = adj @ bufA + b1   (batched over 64)
    gemm64_kernel<<<dim3(4, 4, 64), 256>>>(
        SEL_EXT, adj, SADJ, SEL_BUFA, nullptr, SX, SEL_BUFB, nullptr, SX,
        b1, nullptr, nullptr, 256, 256, 256);
    // bufA = bufB @ W2
    gemm64_kernel<<<dim3(4, MBL / 64, 1), 256>>>(
        SEL_BUFB, nullptr, 0, SEL_EXT, W2, 0, SEL_BUFA, nullptr, 0,
        nullptr, nullptr, nullptr, MBL, 256, 256);
    // bufB = adj @ bufA + b2
    gemm64_kernel<<<dim3(4, 4, 64), 256>>>(
        SEL_EXT, adj, SADJ, SEL_BUFA, nullptr, SX, SEL_BUFB, nullptr, SX,
        b2, nullptr, nullptr, 256, 256, 256);
    // bufA = mix(bufB, eps, agg[cur]+bg)
    mix_kernel<<<2048, 256>>>(cur_node, bg, eps);
    // xi = bufA @ WihT + bih
    gemm64_kernel<<<dim3(12, MBL / 64, 1), 256>>>(
        SEL_BUFA, nullptr, 0, SEL_WIHT, nullptr, 0, SEL_XI, nullptr, 0,
        bih, nullptr, nullptr, MBL, 768, 256);
    // GRU recurrence
    gru_kernel<<<32, 256>>>(bhh);
    // out = relu(hT @ fc1W^T + fc1b)
    fc_kernel<<<64, 256>>>(fc1b, out);
}

// round 4
// speedup vs baseline: 1.1166x; 1.1166x over previous
#include <cuda_runtime.h>
#include <cstdint>

#define ENTITYN 50000
#define EMBD    256
#define HIDD    256
#define BATCHN  64
#define LSEQ    256
#define NEDGE   800000

// ---------------- scratch (device globals: no allocation allowed) ----------------
__device__ float g_bufA[BATCHN * LSEQ * HIDD];        // 16.8 MB
__device__ float g_bufB[BATCHN * LSEQ * HIDD];        // 16.8 MB
__device__ float g_xi[BATCHN * LSEQ * 3 * HIDD];      // 50 MB
__device__ float g_WihT[HIDD * 3 * HIDD];             // [k][n] = Wih[n][k]
__device__ float g_WhhP[HIDD * 3 * HIDD];             // packed [k][j], row j contiguous
__device__ float g_fc1WT[HIDD * HIDD];                // [k][j] = fc1W[j][k]
__device__ float g_support[ENTITYN * HIDD];           // 51.2 MB (gated path)
__device__ float g_agg[ENTITYN * HIDD];               // 51.2 MB (gated path)
__device__ float g_hT[BATCHN * HIDD];

// Device-side buffer selector: keeps kernel_launch free of cudaGetSymbolAddress.
#define SEL_EXT     0
#define SEL_BUFA    1
#define SEL_BUFB    2
#define SEL_XI      3
#define SEL_WIHT    4
#define SEL_SUPPORT 5

__device__ __forceinline__ float* selptr(int s, const void* ext) {
    switch (s) {
        case SEL_BUFA:    return g_bufA;
        case SEL_BUFB:    return g_bufB;
        case SEL_XI:      return g_xi;
        case SEL_WIHT:    return g_WihT;
        case SEL_SUPPORT: return g_support;
        default:          return (float*)ext;
    }
}

__device__ __forceinline__ uint32_t f2tf32(float x) {
    uint32_t u;
    asm("cvt.rna.tf32.f32 %0, %1;" : "=r"(u) : "f"(x));
    return u;
}

__device__ __forceinline__ void mma_tf32(float* c, const uint32_t* a,
                                         uint32_t b0, uint32_t b1) {
    asm volatile(
        "mma.sync.aligned.m16n8k8.row.col.f32.tf32.tf32.f32 "
        "{%0,%1,%2,%3}, {%4,%5,%6,%7}, {%8,%9}, {%0,%1,%2,%3};"
        : "+f"(c[0]), "+f"(c[1]), "+f"(c[2]), "+f"(c[3])
        : "r"(a[0]), "r"(a[1]), "r"(a[2]), "r"(a[3]), "r"(b0), "r"(b1));
}

// ---------------- weight prep: transposes + packing ----------------
__global__ void prep_kernel(const float* __restrict__ Wih,
                            const float* __restrict__ Whh,
                            const float* __restrict__ fc1W) {
    int stride = gridDim.x * blockDim.x;
    int t0 = blockIdx.x * blockDim.x + threadIdx.x;
    for (int i = t0; i < 256 * 768; i += stride) {
        int k = i / 768, n = i % 768;
        g_WihT[i] = Wih[n * 256 + k];
    }
    for (int i = t0; i < 256 * 768; i += stride) {
        int k = i / 768, r = i % 768;   // r = output row j
        g_WhhP[i] = Whh[r * 256 + k];
    }
    for (int i = t0; i < 256 * 256; i += stride) {
        int k = i / 256, j = i % 256;
        g_fc1WT[i] = fc1W[j * 256 + k];
    }
}

// ---------------- gated GNN path (only runs when eps != 0) ----------------
__global__ void zero_agg_kernel(const float* __restrict__ eps) {
    if (eps[0] == 0.0f) return;
    int stride = gridDim.x * blockDim.x;
    for (int i = blockIdx.x * blockDim.x + threadIdx.x; i < ENTITYN * HIDD; i += stride)
        g_agg[i] = 0.0f;
}

__global__ void scatter_kernel(const int* __restrict__ esrc,
                               const int* __restrict__ edst,
                               const float* __restrict__ ew,
                               const float* __restrict__ eps) {
    if (eps[0] == 0.0f) return;
    long stride = (long)gridDim.x * blockDim.x;
    long total = (long)NEDGE * 64;   // 64 float4 chunks per edge
    for (long i = (long)blockIdx.x * blockDim.x + threadIdx.x; i < total; i += stride) {
        int e = (int)(i >> 6);
        int c = ((int)i & 63) * 4;
        int s = esrc[e], d = edst[e];
        float w = ew[e];
        const float4 v = *(const float4*)&g_support[(long)s * 256 + c];
        float* dst = &g_agg[(long)d * 256 + c];
        atomicAdd(dst + 0, v.x * w);
        atomicAdd(dst + 1, v.y * w);
        atomicAdd(dst + 2, v.z * w);
        atomicAdd(dst + 3, v.w * w);
    }
}

// ---------------- tf32 tensor-core GEMM: C = A@B (+bias)
// optional row gather on A, optional batching via blockIdx.z, optional eps gate.
// Block tile 128x128, K-chunk 32, 8 warps (warp tile 32x64), single-buffered smem.
__global__ void __launch_bounds__(256, 2) mma_gemm_kernel(
    int selA, const void* Aext, long strideA,
    int selB, const void* Bext, long strideB,
    int selC, void* Cext, long strideC,
    const float* __restrict__ bias,
    const int* __restrict__ gidx,
    const float* __restrict__ gate,
    int M, int N, int K)
{
    if (gate != nullptr && gate[0] == 0.0f) return;
    const float* A = selptr(selA, Aext) + (long)blockIdx.z * strideA;
    const float* B = selptr(selB, Bext) + (long)blockIdx.z * strideB;
    float*       C = selptr(selC, Cext) + (long)blockIdx.z * strideC;

    __shared__ uint32_t As[128][36];   // [m][k], pad 36: conflict-free frag LDS
    __shared__ uint32_t Bs[32][132];   // [k][n], pad 132: <=2-way frag LDS

    const int tid  = threadIdx.x;
    const int wid  = tid >> 5, lane = tid & 31;
    const int g    = lane >> 2, t = lane & 3;
    const int wm   = wid >> 1, wn = wid & 1;
    const int m0   = blockIdx.y * 128, n0 = blockIdx.x * 128;

    // Pre-resolve A row indices (4 float4 loads per thread per chunk; rows fixed)
    long agrow[4];
#pragma unroll
    for (int i = 0; i < 4; i++) {
        int f = tid + i * 256;
        int m = m0 + (f >> 3);
        if (m < M) agrow[i] = gidx ? (long)gidx[m] : (long)m;
        else       agrow[i] = -1;
    }

    float acc[2][8][4];
#pragma unroll
    for (int mt = 0; mt < 2; mt++)
#pragma unroll
        for (int nt = 0; nt < 8; nt++)
#pragma unroll
            for (int q = 0; q < 4; q++) acc[mt][nt][q] = 0.0f;

    for (int k0 = 0; k0 < K; k0 += 32) {
        // stage A tile 128x32 (tf32-converted)
#pragma unroll
        for (int i = 0; i < 4; i++) {
            int f = tid + i * 256;
            int row = f >> 3, k4 = (f & 7) * 4;
            float4 v = make_float4(0.f, 0.f, 0.f, 0.f);
            if (agrow[i] >= 0) v = *(const float4*)(A + agrow[i] * K + k0 + k4);
            uint4 u = make_uint4(f2tf32(v.x), f2tf32(v.y), f2tf32(v.z), f2tf32(v.w));
            *(uint4*)&As[row][k4] = u;
        }
        // stage B tile 32x128
#pragma unroll
        for (int i = 0; i < 4; i++) {
            int f = tid + i * 256;
            int kk = f >> 5, n4 = (f & 31) * 4;
            float4 v = *(const float4*)(B + (long)(k0 + kk) * N + n0 + n4);
            uint4 u = make_uint4(f2tf32(v.x), f2tf32(v.y), f2tf32(v.z), f2tf32(v.w));
            *(uint4*)&Bs[kk][n4] = u;
        }
        __syncthreads();

#pragma unroll
        for (int ks = 0; ks < 32; ks += 8) {
            uint32_t af[2][4];
#pragma unroll
            for (int mt = 0; mt < 2; mt++) {
                int r = wm * 32 + mt * 16 + g;
                af[mt][0] = As[r    ][ks + t];
                af[mt][1] = As[r + 8][ks + t];
                af[mt][2] = As[r    ][ks + t + 4];
                af[mt][3] = As[r + 8][ks + t + 4];
            }
#pragma unroll
            for (int nt = 0; nt < 8; nt++) {
                int c = wn * 64 + nt * 8 + g;
                uint32_t b0 = Bs[ks + t    ][c];
                uint32_t b1 = Bs[ks + t + 4][c];
                mma_tf32(acc[0][nt], af[0], b0, b1);
                mma_tf32(acc[1][nt], af[1], b0, b1);
            }
        }
        __syncthreads();
    }

    // epilogue: c0:(g,2t) c1:(g,2t+1) c2:(g+8,2t) c3:(g+8,2t+1)
#pragma unroll
    for (int mt = 0; mt < 2; mt++) {
        int r0 = m0 + wm * 32 + mt * 16 + g;
#pragma unroll
        for (int nt = 0; nt < 8; nt++) {
            int c = n0 + wn * 64 + nt * 8 + 2 * t;
            float b0v = 0.f, b1v = 0.f;
            if (bias) { b0v = bias[c]; b1v = bias[c + 1]; }
            if (r0 < M) {
                float2 o = make_float2(acc[mt][nt][0] + b0v, acc[mt][nt][1] + b1v);
                *(float2*)(C + (long)r0 * N + c) = o;
            }
            int r1 = r0 + 8;
            if (r1 < M) {
                float2 o = make_float2(acc[mt][nt][2] + b0v, acc[mt][nt][3] + b1v);
                *(float2*)(C + (long)r1 * N + c) = o;
            }
        }
    }
}

// ---------------- eps mix: bufA = (1-eps)*bufB + eps*leaky(agg[cur]+bg) ----------------
__global__ void mix_kernel(const int* __restrict__ cur,
                           const float* __restrict__ bg,
                           const float* __restrict__ eps) {
    float e = eps[0];
    int stride = gridDim.x * blockDim.x;
    for (int i = blockIdx.x * blockDim.x + threadIdx.x; i < BATCHN * LSEQ * HIDD; i += stride) {
        float v = g_bufB[i];
        if (e != 0.0f) {
            int row = i >> 8, col = i & 255;
            int cn = cur[row];
            float a = g_agg[(long)cn * 256 + col] + bg[col];
            a = a > 0.0f ? a : 0.2f * a;
            v = (1.0f - e) * v + e * a;
        }
        g_bufA[i] = v;
    }
}

// ---------------- GRU: 32 blocks, 2 batch elements per block ----------------
__global__ void __launch_bounds__(256, 1) gru_kernel(const float* __restrict__ bhh) {
    __shared__ float h0[256], h1[256];
    __shared__ float gh0[768], gh1[768];
    __shared__ float sb[768];

    const int tid = threadIdx.x;
    const int b0 = blockIdx.x * 2, b1 = b0 + 1;

    h0[tid] = 0.0f;
    h1[tid] = 0.0f;
    for (int j = tid; j < 768; j += 256) sb[j] = bhh[j];
    __syncthreads();

    const float4* Wp = (const float4*)g_WhhP;   // [k][192] float4

    for (int t = 0; t < 256; t++) {
        if (tid < 192) {
            float a00 = 0.f, a01 = 0.f, a02 = 0.f, a03 = 0.f;
            float a10 = 0.f, a11 = 0.f, a12 = 0.f, a13 = 0.f;
            const float4* wp = Wp + tid;
#pragma unroll 16
            for (int k = 0; k < 256; k++) {
                float4 w = wp[k * 192];
                float x0 = h0[k], x1 = h1[k];
                a00 += w.x * x0; a01 += w.y * x0; a02 += w.z * x0; a03 += w.w * x0;
                a10 += w.x * x1; a11 += w.y * x1; a12 += w.z * x1; a13 += w.w * x1;
            }
            ((float4*)gh0)[tid] = make_float4(a00, a01, a02, a03);
            ((float4*)gh1)[tid] = make_float4(a10, a11, a12, a13);
        }
        __syncthreads();
        {
            const int j = tid;
            const float* xb0 = g_xi + ((long)b0 * 256 + t) * 768;
            const float* xb1 = g_xi + ((long)b1 * 256 + t) * 768;

            float ir = xb0[j], iz = xb0[256 + j], in0 = xb0[512 + j];
            float hr = gh0[j] + sb[j];
            float hz = gh0[256 + j] + sb[256 + j];
            float hn = gh0[512 + j] + sb[512 + j];
            float r = 1.0f / (1.0f + __expf(-(ir + hr)));
            float z = 1.0f / (1.0f + __expf(-(iz + hz)));
            float n = tanhf(in0 + r * hn);
            float hnew0 = (1.0f - z) * n + z * h0[j];

            ir = xb1[j]; iz = xb1[256 + j]; in0 = xb1[512 + j];
            hr = gh1[j] + sb[j];
            hz = gh1[256 + j] + sb[256 + j];
            hn = gh1[512 + j] + sb[512 + j];
            r = 1.0f / (1.0f + __expf(-(ir + hr)));
            z = 1.0f / (1.0f + __expf(-(iz + hz)));
            n = tanhf(in0 + r * hn);
            float hnew1 = (1.0f - z) * n + z * h1[j];

            h0[j] = hnew0;   // safe: only this thread touches h[j] in epilogue
            h1[j] = hnew1;
        }
        __syncthreads();
    }
    g_hT[(long)b0 * 256 + tid] = h0[tid];
    g_hT[(long)b1 * 256 + tid] = h1[tid];
}

// ---------------- final fc1 + relu ----------------
__global__ void fc_kernel(const float* __restrict__ fc1b, float* __restrict__ out) {
    __shared__ float hs[HIDD];
    const int b = blockIdx.x, j = threadIdx.x;
    hs[j] = g_hT[b * HIDD + j];
    __syncthreads();
    float acc = 0.0f;
#pragma unroll 8
    for (int k = 0; k < HIDD; k++) acc += hs[k] * g_fc1WT[k * HIDD + j];
    acc += fc1b[j];
    out[b * HIDD + j] = acc > 0.0f ? acc : 0.0f;
}

// ---------------- launcher: kernel launches ONLY, no other CUDA API ----------------
extern "C" void kernel_launch(void* const* d_in, const int* in_sizes, int n_in,
                              void* d_out, int out_size) {
    const int*   neighbors = (const int*)  d_in[0];
    const float* adj       = (const float*)d_in[1];
    const int*   cur_node  = (const int*)  d_in[2];
    const int*   edge_src  = (const int*)  d_in[3];
    const int*   edge_dst  = (const int*)  d_in[4];
    const float* edge_w    = (const float*)d_in[5];
    const float* emb       = (const float*)d_in[6];
    const float* Wg        = (const float*)d_in[7];
    const float* bg        = (const float*)d_in[8];
    const float* W1        = (const float*)d_in[9];
    const float* b1        = (const float*)d_in[10];
    const float* W2        = (const float*)d_in[11];
    const float* b2        = (const float*)d_in[12];
    const float* eps       = (const float*)d_in[13];
    const float* Wih       = (const float*)d_in[14];
    const float* Whh       = (const float*)d_in[15];
    const float* bih       = (const float*)d_in[16];
    const float* bhh       = (const float*)d_in[17];
    const float* fc1W      = (const float*)d_in[18];
    const float* fc1b      = (const float*)d_in[19];
    float* out = (float*)d_out;

    const int  MBL  = BATCHN * LSEQ;        // 16384
    const long SADJ = (long)LSEQ * LSEQ;    // 65536
    const long SX   = (long)LSEQ * HIDD;    // 65536

    // weight prep
    prep_kernel<<<256, 256>>>(Wih, Whh, fc1W);

    // gated global-GNN path (no-op when eps == 0)
    zero_agg_kernel<<<2048, 256>>>(eps);
    mma_gemm_kernel<<<dim3(2, (ENTITYN + 127) / 128, 1), 256>>>(
        SEL_EXT, emb, 0, SEL_EXT, Wg, 0, SEL_SUPPORT, nullptr, 0,
        nullptr, nullptr, eps, ENTITYN, 256, 256);
    scatter_kernel<<<4096, 256>>>(edge_src, edge_dst, edge_w, eps);

    // bufA = emb[neighbors] @ W1
    mma_gemm_kernel<<<dim3(2, MBL / 128, 1), 256>>>(
        SEL_EXT, emb, 0, SEL_EXT, W1, 0, SEL_BUFA, nullptr, 0,
        nullptr, neighbors, nullptr, MBL, 256, 256);
    // bufB = adj @ bufA + b1   (batched over 64)
    mma_gemm_kernel<<<dim3(2, 2, 64), 256>>>(
        SEL_EXT, adj, SADJ, SEL_BUFA, nullptr, SX, SEL_BUFB, nullptr, SX,
        b1, nullptr, nullptr, 256, 256, 256);
    // bufA = bufB @ W2
    mma_gemm_kernel<<<dim3(2, MBL / 128, 1), 256>>>(
        SEL_BUFB, nullptr, 0, SEL_EXT, W2, 0, SEL_BUFA, nullptr, 0,
        nullptr, nullptr, nullptr, MBL, 256, 256);
    // bufB = adj @ bufA + b2
    mma_gemm_kernel<<<dim3(2, 2, 64), 256>>>(
        SEL_EXT, adj, SADJ, SEL_BUFA, nullptr, SX, SEL_BUFB, nullptr, SX,
        b2, nullptr, nullptr, 256, 256, 256);
    // bufA = mix(bufB, eps, agg[cur]+bg)
    mix_kernel<<<2048, 256>>>(cur_node, bg, eps);
    // xi = bufA @ WihT + bih
    mma_gemm_kernel<<<dim3(6, MBL / 128, 1), 256>>>(
        SEL_BUFA, nullptr, 0, SEL_WIHT, nullptr, 0, SEL_XI, nullptr, 0,
        bih, nullptr, nullptr, MBL, 768, 256);
    // GRU recurrence
    gru_kernel<<<32, 256>>>(bhh);
    // out = relu(hT @ fc1W^T + fc1b)
    fc_kernel<<<64, 256>>>(fc1b, out);
}